// round 1
// baseline (speedup 1.0000x reference)
#include <cuda_runtime.h>

#define BB 512
#define TT 8192
#define KW 5
#define NCH 32              // speculative chunks per row
#define CL  (TT / NCH)      // 256 steps per chunk
#define WARM 256            // warmup steps (trajectory coupling)

// One LIF step matching XLA semantics exactly:
//   c = RN(RN(d*v) + x)   (separate mul/add, no FMA contraction)
//   spike = (c >= 1)
//   v' = spike ? c - 1 : c   (c-1 exact by Sterbenz for c in [1,2))
__device__ __forceinline__ float stepw(float& v, float d, float x, float w) {
    float c = __fadd_rn(__fmul_rn(d, v), x);
    bool s = (c >= 1.0f);
    v = s ? __fadd_rn(c, -1.0f) : c;
    return s ? w : 0.0f;
}

__global__ __launch_bounds__(128, 1) void spike_stage1(
    const float* __restrict__ amp, const float* __restrict__ pitch,
    const float* __restrict__ boundary, const float* __restrict__ decay,
    const float* __restrict__ weights, float* __restrict__ cnt)
{
    int tid = blockIdx.x * 128 + threadIdx.x;   // 16384 threads total
    int b = tid >> 5;                           // row (warp = 32 chunks of one row)
    int k = tid & 31;                           // chunk index
    if (b >= BB) return;

    float d0 = __ldg(decay),     d1 = __ldg(decay + 1),   d2 = __ldg(decay + 2);
    float w0 = __ldg(weights),   w1 = __ldg(weights + 1), w2 = __ldg(weights + 2);

    int t_real = k * CL;
    int warm   = (k == 0) ? 0 : WARM;
    long base  = (long)b * TT;

    const float4* pa = (const float4*)(amp      + base + t_real - warm);
    const float4* pp = (const float4*)(pitch    + base + t_real - warm);
    const float4* pb = (const float4*)(boundary + base + t_real - warm);
    float4*       pc = (float4*)      (cnt      + base + t_real);

    float v0 = 0.f, v1 = 0.f, v2 = 0.f;

    // ---- warmup: run recurrence, discard spikes (trajectory couples to exact) ----
    int nw = warm >> 2;
    #pragma unroll 4
    for (int i = 0; i < nw; i++) {
        float4 xa = pa[i], xp = pp[i], xb = pb[i];
        stepw(v0, d0, xa.x, w0); stepw(v1, d1, xp.x, w1); stepw(v2, d2, xb.x, w2);
        stepw(v0, d0, xa.y, w0); stepw(v1, d1, xp.y, w1); stepw(v2, d2, xb.y, w2);
        stepw(v0, d0, xa.z, w0); stepw(v1, d1, xp.z, w1); stepw(v2, d2, xb.z, w2);
        stepw(v0, d0, xa.w, w0); stepw(v1, d1, xp.w, w1); stepw(v2, d2, xb.w, w2);
    }
    pa += nw; pp += nw; pb += nw;

    // ---- real chunk: write weighted spike counts ----
    #pragma unroll 4
    for (int i = 0; i < CL / 4; i++) {
        float4 xa = pa[i], xp = pp[i], xb = pb[i];
        float4 o;
        o.x = stepw(v0, d0, xa.x, w0) + stepw(v1, d1, xp.x, w1) + stepw(v2, d2, xb.x, w2);
        o.y = stepw(v0, d0, xa.y, w0) + stepw(v1, d1, xp.y, w1) + stepw(v2, d2, xb.y, w2);
        o.z = stepw(v0, d0, xa.z, w0) + stepw(v1, d1, xp.z, w1) + stepw(v2, d2, xb.z, w2);
        o.w = stepw(v0, d0, xa.w, w0) + stepw(v1, d1, xp.w, w1) + stepw(v2, d2, xb.w, w2);
        pc[i] = o;
    }
}

// One block per row: stable top-5 (value desc, index asc = lax.top_k semantics),
// in-place normalization of sal, mu computation.
__global__ __launch_bounds__(256, 1) void spike_stage2(float* __restrict__ out)
{
    __shared__ float sh[TT];     // 32 KB row buffer
    __shared__ float rv[256];
    __shared__ int   ri[256];

    int b  = blockIdx.x;
    int tx = threadIdx.x;
    float* sal = out + BB + (long)b * TT;

    for (int t = tx; t < TT; t += 256) sh[t] = sal[t];
    __syncthreads();

    float vals[KW]; int idxs[KW];

    for (int j = 0; j < KW; j++) {
        float best = -1e30f; int bi = TT;
        for (int t = tx; t < TT; t += 256) {
            float v = sh[t];
            if (v > best) { best = v; bi = t; }   // ascending t => earliest tie kept
        }
        rv[tx] = best; ri[tx] = bi;
        __syncthreads();
        for (int s = 128; s > 0; s >>= 1) {
            if (tx < s) {
                float ov = rv[tx + s]; int oi = ri[tx + s];
                if (ov > rv[tx] || (ov == rv[tx] && oi < ri[tx])) { rv[tx] = ov; ri[tx] = oi; }
            }
            __syncthreads();
        }
        vals[j] = rv[0]; idxs[j] = ri[0];
        __syncthreads();

        if (j == 0) {
            // normalize sal in place using original (unmasked) values
            float norm = __fadd_rn(vals[0], 1e-6f);
            for (int t = tx; t < TT; t += 256) sal[t] = sh[t] / norm;
        }
        if (tx == 0) sh[idxs[j]] = -1e30f;   // mask winner for next pass
        __syncthreads();
    }

    if (tx == 0) {
        float norm = __fadd_rn(vals[0], 1e-6f);
        float avg = 0.f;
        #pragma unroll
        for (int j = 0; j < KW; j++) avg += vals[j] / norm;
        avg *= (1.0f / KW);
        float mu = 0.5f + 2.0f * tanhf(1.8f * avg);
        out[b] = mu;                                    // mu_scalar region
        float* oidx = out + BB + (long)BB * TT + b * KW; // topk_idx region (as f32)
        #pragma unroll
        for (int j = 0; j < KW; j++) oidx[j] = (float)idxs[j];
    }
}

extern "C" void kernel_launch(void* const* d_in, const int* in_sizes, int n_in,
                              void* d_out, int out_size) {
    const float* amp      = (const float*)d_in[0];
    const float* pitch    = (const float*)d_in[1];
    const float* boundary = (const float*)d_in[2];
    const float* decay    = (const float*)d_in[3];
    const float* weights  = (const float*)d_in[4];
    float* out = (float*)d_out;

    // Output layout: [mu (512)] [sal (512*8192)] [topk_idx (512*5)]
    spike_stage1<<<(BB * NCH) / 128, 128>>>(amp, pitch, boundary, decay, weights, out + BB);
    spike_stage2<<<BB, 256>>>(out);
}

// round 3
// speedup vs baseline: 1.1238x; 1.1238x over previous
#include <cuda_runtime.h>

#define BB 512
#define TT 8192
#define KW 5
#define CL 128
#define NTH 64
#define WARM 192

// Swizzles: odd word-stride (133) across lanes -> conflict-free scalar LDS/STS.
#define PADW(t) ((t) + 5 * ((t) >> 7))
// Byte codes: stride 132 bytes (4-aligned so 4 codes load as one u32).
#define PADB(t) ((t) + 4 * ((t) >> 7))

#define SZF (TT + 5 * (TT / 128))          // 8512 words per float array
#define SZC (TT + 4 * (TT / 128))          // 8448 bytes for codes
#define OFF_C   (3 * SZF * 4)              // 102144
#define OFF_MK  (OFF_C + SZC)              // 110592
#define OFF_LUT (OFF_MK + NTH * KW * 4)    // 111872
#define OFF_DEN (OFF_LUT + 32)             // 111904
#define SMEM_TOTAL (OFF_DEN + 16)          // 111920 bytes

// s = (c >= 1.0f) ? 1.0f : 0.0f as a single FSET (avoids 13-cyc pred-guard path)
__device__ __forceinline__ float fset_ge1(float c) {
    float r;
    asm("set.ge.f32.f32 %0, %1, 0f3F800000;" : "=f"(r) : "f"(c));
    return r;
}

// Insert packed key into sorted-desc 5-list (FMNMX bubble).
__device__ __forceinline__ void insert5(float kk[KW], float x) {
    kk[4] = fmaxf(kk[4], x);
#pragma unroll
    for (int j = 4; j >= 1; j--) {
        float hi = fmaxf(kk[j - 1], kk[j]);
        float lo = fminf(kk[j - 1], kk[j]);
        kk[j - 1] = hi; kk[j] = lo;
    }
}

__global__ void __launch_bounds__(NTH, 1) fused_kernel(
    const float* __restrict__ amp, const float* __restrict__ pitch,
    const float* __restrict__ boundary, const float* __restrict__ decay,
    const float* __restrict__ weights, float* __restrict__ out)
{
    extern __shared__ char sm[];
    float* fA = (float*)sm;
    float* fP = fA + SZF;
    float* fB = fA + 2 * SZF;
    unsigned char* codes = (unsigned char*)(sm + OFF_C);
    float* mk   = (float*)(sm + OFF_MK);
    float* lut  = (float*)(sm + OFF_LUT);
    float* denp = (float*)(sm + OFF_DEN);

    int b   = blockIdx.x;
    int tid = threadIdx.x;
    long base = (long)b * TT;

    float d0 = __ldg(decay),   d1 = __ldg(decay + 1),   d2 = __ldg(decay + 2);
    float w0 = __ldg(weights), w1 = __ldg(weights + 1), w2 = __ldg(weights + 2);

    // ---- stage row into swizzled smem (coalesced gmem reads) ----
    {
        const float4* ga = (const float4*)(amp      + base);
        const float4* gp = (const float4*)(pitch    + base);
        const float4* gb = (const float4*)(boundary + base);
        for (int j = tid; j < TT / 4; j += NTH) {
            float4 va = ga[j], vp = gp[j], vb = gb[j];
            int t = 4 * j;
            int s = PADW(t);        // t%4==0: 4 slots contiguous within 128-block
            fA[s] = va.x; fA[s+1] = va.y; fA[s+2] = va.z; fA[s+3] = va.w;
            fP[s] = vp.x; fP[s+1] = vp.y; fP[s+2] = vp.z; fP[s+3] = vp.w;
            fB[s] = vb.x; fB[s+1] = vb.y; fB[s+2] = vb.z; fB[s+3] = vb.w;
        }
        if (tid == 0) {
#pragma unroll
            for (int c = 0; c < 8; c++)
                lut[c] = (c & 1 ? w0 : 0.f) + (c & 2 ? w1 : 0.f) + (c & 4 ? w2 : 0.f);
        }
    }
    __syncthreads();

    // ---- LIF recurrence: warmup (speculative coupling) + real chunk ----
    int t0   = tid * CL;
    int warm = t0 < WARM ? t0 : WARM;     // tid 0: exact; tid 1: 128 exact; >=2: 192 spec
    float v0 = 0.f, v1 = 0.f, v2 = 0.f;

    {   // warmup: segments aligned to 128-word blocks (warm in {0,128,192})
        int t = t0 - warm;
        int rem = warm;
        while (rem > 0) {
            int run = 128 - (t & 127);
            if (run > rem) run = rem;
            int idx = PADW(t);
#pragma unroll 8
            for (int i = 0; i < run; i++) {
                float xa = fA[idx + i], xp = fP[idx + i], xb = fB[idx + i];
                float c0 = __fadd_rn(__fmul_rn(d0, v0), xa);
                float c1 = __fadd_rn(__fmul_rn(d1, v1), xp);
                float c2 = __fadd_rn(__fmul_rn(d2, v2), xb);
                v0 = __fadd_rn(c0, -fset_ge1(c0));
                v1 = __fadd_rn(c1, -fset_ge1(c1));
                v2 = __fadd_rn(c2, -fset_ge1(c2));
            }
            t += run; rem -= run;
        }
    }
    {   // real chunk: exactly 128 steps starting at a 128-block boundary
        int idx  = PADW(t0);
        int cidx = PADB(t0);
#pragma unroll 8
        for (int i = 0; i < CL; i++) {
            float xa = fA[idx + i], xp = fP[idx + i], xb = fB[idx + i];
            float c0 = __fadd_rn(__fmul_rn(d0, v0), xa);
            float c1 = __fadd_rn(__fmul_rn(d1, v1), xp);
            float c2 = __fadd_rn(__fmul_rn(d2, v2), xb);
            float s0 = fset_ge1(c0), s1 = fset_ge1(c1), s2 = fset_ge1(c2);
            v0 = __fadd_rn(c0, -s0);
            v1 = __fadd_rn(c1, -s1);
            v2 = __fadd_rn(c2, -s2);
            float cf = __fmaf_rn(s2, 4.f, __fmaf_rn(s1, 2.f, s0));
            codes[cidx + i] = (unsigned char)__float2int_rn(cf);
        }
    }
    __syncthreads();

    // ---- pass 1: decode own chunk, stash weighted counts, per-thread top-5 ----
    float kk[KW];
#pragma unroll
    for (int j = 0; j < KW; j++) kk[j] = -3.0e38f;
    {
        int cbase = PADB(t0);
        for (int j = 0; j < CL; j += 4) {
            unsigned int w = *(const unsigned int*)(codes + cbase + j);
#pragma unroll
            for (int jj = 0; jj < 4; jj++) {
                int tcur = t0 + j + jj;
                float val = lut[(w >> (8 * jj)) & 7];
                fA[PADW(tcur)] = val;                       // reuse fA as val stash
                float key = __fmaf_rn(val, 8192.f, -(float)tcur);
                if (key > kk[4]) insert5(kk, key);
            }
        }
    }

    // ---- block tree-merge of sorted-5 packed-key lists ----
#pragma unroll
    for (int j = 0; j < KW; j++) mk[tid * KW + j] = kk[j];
    __syncthreads();
    for (int s = NTH / 2; s >= 1; s >>= 1) {
        if (tid < s) {
#pragma unroll
            for (int j = 0; j < KW; j++) {
                float x = mk[(tid + s) * KW + j];
                if (x > kk[4]) insert5(kk, x);
            }
#pragma unroll
            for (int j = 0; j < KW; j++) mk[tid * KW + j] = kk[j];
        }
        __syncthreads();
    }

    // ---- thread 0: decode winners, mu, topk_idx; broadcast denom ----
    if (tid == 0) {
        float vmax = ceilf(kk[0] * (1.0f / 8192.0f));   // exact: integer counts
        float den  = __fadd_rn(vmax, 1e-6f);
        float ssum = 0.f;
        float* oi = out + BB + (long)BB * TT + b * KW;
#pragma unroll
        for (int j = 0; j < KW; j++) {
            float vj = ceilf(kk[j] * (1.0f / 8192.0f));
            float ij = __fmaf_rn(vj, 8192.0f, -kk[j]);  // exact integer index
            oi[j] = ij;
            ssum = __fadd_rn(ssum, vj / den);
        }
        float avg = ssum * 0.2f;
        out[b] = 0.5f + 2.0f * tanhf(1.8f * avg);
        *denp = den;
    }
    __syncthreads();

    // ---- pass 2: normalize + coalesced scalar store of sal ----
    float invd = 1.0f / (*denp);
    float* sal = out + BB + base;
    for (int j = tid; j < TT; j += NTH)
        sal[j] = fA[PADW(j)] * invd;
}

extern "C" void kernel_launch(void* const* d_in, const int* in_sizes, int n_in,
                              void* d_out, int out_size) {
    const float* amp      = (const float*)d_in[0];
    const float* pitch    = (const float*)d_in[1];
    const float* boundary = (const float*)d_in[2];
    const float* decay    = (const float*)d_in[3];
    const float* weights  = (const float*)d_in[4];
    float* out = (float*)d_out;

    cudaFuncSetAttribute(fused_kernel,
                         cudaFuncAttributeMaxDynamicSharedMemorySize, SMEM_TOTAL);
    // Output layout: [mu (512)] [sal (512*8192)] [topk_idx (512*5) as f32]
    fused_kernel<<<BB, NTH, SMEM_TOTAL>>>(amp, pitch, boundary, decay, weights, out);
}

// round 4
// speedup vs baseline: 2.0579x; 1.8312x over previous
#include <cuda_runtime.h>
#include <cstdint>

#define BB 512
#define TT 8192
#define KW 5
#define NTH 128
#define WPB 4                 // warps per block
#define WARP_T 2048           // steps per warp
#define WARP_F4 512           // float4s per warp
#define HALO_F4 48            // 192-step speculative warmup halo
#define SLICE_F4 (WARP_F4 + HALO_F4)   // 560
#define CLF4 16               // float4s per lane chunk (64 steps)

// XOR swizzle on float4 index within a slice: 16B-aligned, conflict-free
// (8-lane phases hit distinct bank-quads for lane-stride-16 and stride-1 patterns).
#define QS(u) ((u) ^ ((((unsigned)(u)) >> 4) & 7))

#define SMEM_DYN (WPB * 3 * SLICE_F4 * 16)   // 107,520 bytes

__device__ __forceinline__ uint32_t smem_u32(const void* p) {
    uint32_t a;
    asm("{ .reg .u64 t; cvta.to.shared.u64 t, %1; cvt.u32.u64 %0, t; }"
        : "=r"(a) : "l"(p));
    return a;
}

__device__ __forceinline__ float fset_ge1(float c) {
    float r;
    asm("set.ge.f32.f32 %0, %1, 0f3F800000;" : "=f"(r) : "f"(c));
    return r;
}

__device__ __forceinline__ void insert5(float kk[KW], float x) {
    kk[4] = fmaxf(kk[4], x);
#pragma unroll
    for (int j = 4; j >= 1; j--) {
        float hi = fmaxf(kk[j - 1], kk[j]);
        float lo = fminf(kk[j - 1], kk[j]);
        kk[j - 1] = hi; kk[j] = lo;
    }
}

// Warm step: state only. Exact XLA semantics (separate mul/add; Sterbenz-exact c-1).
#define WSTEP(xa, xp, xb) do {                        \
    float c0 = __fadd_rn(__fmul_rn(d0, v0), (xa));    \
    float c1 = __fadd_rn(__fmul_rn(d1, v1), (xp));    \
    float c2 = __fadd_rn(__fmul_rn(d2, v2), (xb));    \
    v0 = __fadd_rn(c0, -fset_ge1(c0));                \
    v1 = __fadd_rn(c1, -fset_ge1(c1));                \
    v2 = __fadd_rn(c2, -fset_ge1(c2));                \
} while (0)

// Real step: returns weighted spike sum.
__device__ __forceinline__ float rstep(float& v0, float& v1, float& v2,
                                       float d0, float d1, float d2,
                                       float w0, float w1, float w2,
                                       float xa, float xp, float xb) {
    float c0 = __fadd_rn(__fmul_rn(d0, v0), xa);
    float c1 = __fadd_rn(__fmul_rn(d1, v1), xp);
    float c2 = __fadd_rn(__fmul_rn(d2, v2), xb);
    float s0 = fset_ge1(c0), s1 = fset_ge1(c1), s2 = fset_ge1(c2);
    v0 = __fadd_rn(c0, -s0);
    v1 = __fadd_rn(c1, -s1);
    v2 = __fadd_rn(c2, -s2);
    return __fmaf_rn(s2, w2, __fmaf_rn(s1, w1, __fmul_rn(s0, w0)));
}

__global__ void __launch_bounds__(NTH, 1) fused_kernel(
    const float* __restrict__ amp, const float* __restrict__ pitch,
    const float* __restrict__ boundary, const float* __restrict__ decay,
    const float* __restrict__ weights, float* __restrict__ out)
{
    extern __shared__ float4 sm4[];
    __shared__ float mk[NTH * KW];
    __shared__ float s_den;

    int b   = blockIdx.x;
    int tid = threadIdx.x;
    int w   = tid >> 5;
    int l   = tid & 31;
    long rowf4 = (long)b * (TT / 4);

    float d0 = __ldg(decay),   d1 = __ldg(decay + 1),   d2 = __ldg(decay + 2);
    float w0 = __ldg(weights), w1 = __ldg(weights + 1), w2 = __ldg(weights + 2);

    float4* SA = sm4 + (w * 3 + 0) * SLICE_F4;
    float4* SP = sm4 + (w * 3 + 1) * SLICE_F4;
    float4* SB = sm4 + (w * 3 + 2) * SLICE_F4;
    uint32_t sa_u = smem_u32(SA), sp_u = smem_u32(SP), sb_u = smem_u32(SB);

    const float4* gA = (const float4*)amp      + rowf4;
    const float4* gP = (const float4*)pitch    + rowf4;
    const float4* gB = (const float4*)boundary + rowf4;

    // ---- issue all slice loads async (warp-autonomous) ----
    int g0 = w * WARP_F4 - HALO_F4;
    for (int j = l; j < SLICE_F4; j += 32) {
        int src = g0 + j;
        uint32_t off = (uint32_t)QS(j) * 16u;
        if (src >= 0) {
            asm volatile("cp.async.ca.shared.global [%0], [%1], 16;"
                         :: "r"(sa_u + off), "l"(gA + src));
            asm volatile("cp.async.ca.shared.global [%0], [%1], 16;"
                         :: "r"(sp_u + off), "l"(gP + src));
            asm volatile("cp.async.ca.shared.global [%0], [%1], 16;"
                         :: "r"(sb_u + off), "l"(gB + src));
        } else {
            // warp 0 halo: zeros are EXACT (v stays 0 through zero prefix)
            float4 z = make_float4(0.f, 0.f, 0.f, 0.f);
            SA[QS(j)] = z; SP[QS(j)] = z; SB[QS(j)] = z;
        }
    }
    asm volatile("cp.async.wait_all;" ::: "memory");
    __syncwarp();

    // ---- warmup: 192 steps (48 float4s) before own chunk ----
    float v0 = 0.f, v1 = 0.f, v2 = 0.f;
    int ub = CLF4 * l;
#pragma unroll 4
    for (int j = 0; j < HALO_F4; j++) {
        int u = QS(ub + j);
        float4 xa = SA[u], xp = SP[u], xb = SB[u];
        WSTEP(xa.x, xp.x, xb.x);
        WSTEP(xa.y, xp.y, xb.y);
        WSTEP(xa.z, xp.z, xb.z);
        WSTEP(xa.w, xp.w, xb.w);
    }
    __syncwarp();   // all warm reads done before any stash writes

    // ---- real chunk: 64 steps; stash vals in place; inline top-5 ----
    float kk[KW];
#pragma unroll
    for (int j = 0; j < KW; j++) kk[j] = -3.0e38f;
    int tg0 = w * WARP_T + l * 64;

#pragma unroll 4
    for (int j = 0; j < CLF4; j++) {
        int u = QS(ub + HALO_F4 + j);
        float4 xa = SA[u], xp = SP[u], xb = SB[u];
        float4 val;
        val.x = rstep(v0, v1, v2, d0, d1, d2, w0, w1, w2, xa.x, xp.x, xb.x);
        val.y = rstep(v0, v1, v2, d0, d1, d2, w0, w1, w2, xa.y, xp.y, xb.y);
        val.z = rstep(v0, v1, v2, d0, d1, d2, w0, w1, w2, xa.z, xp.z, xb.z);
        val.w = rstep(v0, v1, v2, d0, d1, d2, w0, w1, w2, xa.w, xp.w, xb.w);
        SA[u] = val;   // same-lane same-address overwrite: safe

        float base = -(float)(tg0 + 4 * j);
        float k0 = __fmaf_rn(val.x, 8192.f, base);
        float k1 = __fmaf_rn(val.y, 8192.f, base - 1.f);
        float k2 = __fmaf_rn(val.z, 8192.f, base - 2.f);
        float k3 = __fmaf_rn(val.w, 8192.f, base - 3.f);
        float m = fmaxf(fmaxf(k0, k1), fmaxf(k2, k3));
        if (m > kk[4]) { insert5(kk, k0); insert5(kk, k1); insert5(kk, k2); insert5(kk, k3); }
    }

    // ---- block tree-merge of sorted-5 packed-key lists ----
#pragma unroll
    for (int j = 0; j < KW; j++) mk[tid * KW + j] = kk[j];
    __syncthreads();
    for (int s = NTH / 2; s >= 1; s >>= 1) {
        if (tid < s) {
#pragma unroll
            for (int j = 0; j < KW; j++) {
                float x = mk[(tid + s) * KW + j];
                if (x > kk[4]) insert5(kk, x);
            }
#pragma unroll
            for (int j = 0; j < KW; j++) mk[tid * KW + j] = kk[j];
        }
        __syncthreads();
    }

    // ---- thread 0: decode winners, mu, topk_idx; broadcast denom ----
    if (tid == 0) {
        float vmax = ceilf(kk[0] * (1.0f / 8192.0f));   // exact: integer counts
        float den  = __fadd_rn(vmax, 1e-6f);
        float ssum = 0.f;
        float* oi = out + BB + (long)BB * TT + b * KW;
#pragma unroll
        for (int j = 0; j < KW; j++) {
            float vj = ceilf(kk[j] * (1.0f / 8192.0f));
            float ij = __fmaf_rn(vj, 8192.0f, -kk[j]);  // exact integer index
            oi[j] = ij;
            ssum = __fadd_rn(ssum, vj / den);
        }
        float avg = ssum * 0.2f;
        out[b] = 0.5f + 2.0f * tanhf(1.8f * avg);
        s_den = den;
    }
    __syncthreads();

    // ---- writeback: coalesced float4 stores of normalized sal ----
    float inv = 1.0f / s_den;
    float4* go = (float4*)(out + BB) + rowf4 + w * WARP_F4;
#pragma unroll 4
    for (int i = 0; i < 16; i++) {
        int o = 32 * i + l;
        float4 v = SA[QS(HALO_F4 + o)];
        go[o] = make_float4(v.x * inv, v.y * inv, v.z * inv, v.w * inv);
    }
}

extern "C" void kernel_launch(void* const* d_in, const int* in_sizes, int n_in,
                              void* d_out, int out_size) {
    const float* amp      = (const float*)d_in[0];
    const float* pitch    = (const float*)d_in[1];
    const float* boundary = (const float*)d_in[2];
    const float* decay    = (const float*)d_in[3];
    const float* weights  = (const float*)d_in[4];
    float* out = (float*)d_out;

    cudaFuncSetAttribute(fused_kernel,
                         cudaFuncAttributeMaxDynamicSharedMemorySize, SMEM_DYN);
    // Output layout: [mu (512)] [sal (512*8192)] [topk_idx (512*5) as f32]
    fused_kernel<<<BB, NTH, SMEM_DYN>>>(amp, pitch, boundary, decay, weights, out);
}